// round 9
// baseline (speedup 1.0000x reference)
#include <cuda_runtime.h>
#include <cuda_bf16.h>
#include <math.h>

// ConsensusField3D: per-voxel quaternion slerp + gated blend.
// Shapes: B=2, K=3, D=H=W=96. V = 96^3 = 884736 voxels per batch.
// Vectorized: 2 voxels per thread (float2), all accesses 8B-aligned since
// V is even and every plane offset is a multiple of V.
//
// Inputs (metadata order):
//   d_in[0] U      (B,K,3,D,H,W)  -- UNUSED by reference math
//   d_in[1] r      (B,K,1,D,H,W)
//   d_in[2] q      (B,4,D,H,W)
//   d_in[3] U_ref  (B,K,3,D,H,W)  -- UNUSED
//   d_in[4] r_ref  (B,K,1,D,H,W)
//   d_in[5] q_ref  (B,4,D,H,W)
//   d_in[6] gate_w (4,)
//   d_in[7] gate_b (1,)
//
// Output (flat concat, float32):
//   U_bar (B,3,3,D,H,W)  at offset 0         : U_bar[b][j][i][v] = Rn[v][i][j]
//   r_bar (B,K,1,D,H,W)  at offset B*9V
//   q_out (B,4,D,H,W)    at offset B*9V+B*3V

#define EPSN 1e-6f

static constexpr int Dv = 96;
static constexpr int Vv = Dv * Dv * Dv;   // 884736 (even)
static constexpr int Bv = 2;
static constexpr int Kv = 3;

// Per-voxel math. Inputs: qa/qq raw quats, rv/rrv rates, gate params.
// Outputs: Rn (column-normalized, output-ordered), qo (slerped unit quat), omega.
__device__ __forceinline__ void voxel_math(
    float qa0, float qa1, float qa2, float qa3,
    float qq0, float qq1, float qq2, float qq3,
    float rv0, float rv1, float rv2,
    float rr0, float rr1, float rr2,
    float w0, float w1, float w2, float w3b,
    float Rn[9], float qo[4], float& omega)
{
    // normalize quats (n + EPS in denominator, per reference)
    float na = sqrtf(qa0*qa0 + qa1*qa1 + qa2*qa2 + qa3*qa3) + EPSN;
    float nb = sqrtf(qq0*qq0 + qq1*qq1 + qq2*qq2 + qq3*qq3) + EPSN;
    float ia = 1.0f / na, ib = 1.0f / nb;
    qa0 *= ia; qa1 *= ia; qa2 *= ia; qa3 *= ia;
    qq0 *= ib; qq1 *= ib; qq2 *= ib; qq3 *= ib;

    float dotq = qa0*qq0 + qa1*qq1 + qa2*qq2 + qa3*qq3;
    float cfeat = fminf(fabsf(dotq), 1.0f);

    float rm  = (rv0 + rv1 + rv2) * (1.0f / 3.0f);
    float rmr = (rr0 + rr1 + rr2) * (1.0f / 3.0f);

    float z = fmaf(rm, w0, fmaf(rmr, w1, fmaf(cfeat, w2, w3b)));
    omega = 1.0f / (1.0f + expf(-z));
    float t = omega;

    // slerp with reference semantics
    float sgn = (dotq < 0.0f) ? -1.0f : 1.0f;
    float dcl = fminf(fabsf(dotq), 1.0f - 1e-7f);
    float theta = acosf(dcl);
    float sin_theta = sinf(theta);
    bool  small = sin_theta < 1e-4f;
    float inv_sin = small ? 1.0f : (1.0f / sin_theta);
    float s_t  = sinf(t * theta);
    float s_1t = sinf((1.0f - t) * theta);

    float q1[4]  = { sgn*qq0, sgn*qq1, sgn*qq2, sgn*qq3 };
    float q0a[4] = { qa0, qa1, qa2, qa3 };
#pragma unroll
    for (int c = 0; c < 4; c++) {
        float slerped = (s_t * q0a[c] + s_1t * q1[c]) * inv_sin;
        float lerped  = t * q0a[c] + (1.0f - t) * q1[c];
        qo[c] = small ? lerped : slerped;
    }
    float no = sqrtf(qo[0]*qo[0] + qo[1]*qo[1] + qo[2]*qo[2] + qo[3]*qo[3]) + EPSN;
    float io = 1.0f / no;
#pragma unroll
    for (int c = 0; c < 4; c++) qo[c] *= io;

    // quat -> rotation matrix
    float w = qo[0], x = qo[1], y = qo[2], zq = qo[3];
    float xx = x*x, yy = y*y, z2 = zq*zq;
    float xy = x*y, xz = x*zq, yz = y*zq;
    float wx = w*x, wy = w*y, wz = w*zq;

    float R[3][3];
    R[0][0] = 1.0f - 2.0f*(yy + z2);
    R[0][1] = 2.0f*(xy - wz);
    R[0][2] = 2.0f*(xz + wy);
    R[1][0] = 2.0f*(xy + wz);
    R[1][1] = 1.0f - 2.0f*(xx + z2);
    R[1][2] = 2.0f*(yz - wx);
    R[2][0] = 2.0f*(xz - wy);
    R[2][1] = 2.0f*(yz + wx);
    R[2][2] = 1.0f - 2.0f*(xx + yy);

    // column-normalize (axis=-2): Rn[i][j] = R[i][j] / (||col j|| + EPS)
#pragma unroll
    for (int j = 0; j < 3; j++) {
        float cn = 1.0f / (sqrtf(R[0][j]*R[0][j] + R[1][j]*R[1][j] + R[2][j]*R[2][j]) + EPSN);
#pragma unroll
        for (int i = 0; i < 3; i++) {
            // output layout U_bar[b][j][i][v] -> Rn index (j*3+i)
            Rn[j*3 + i] = R[i][j] * cn;
        }
    }
}

__global__ __launch_bounds__(256)
void consensus_field_kernel(const float* __restrict__ r_in,
                            const float* __restrict__ q_in,
                            const float* __restrict__ r_ref,
                            const float* __restrict__ q_ref,
                            const float* __restrict__ gate_w,
                            const float* __restrict__ gate_b,
                            float* __restrict__ out)
{
    constexpr int H = Vv / 2;                       // float2 elements per plane
    const long long tid = (long long)blockIdx.x * blockDim.x + threadIdx.x;
    const long long total2 = (long long)Bv * H;
    if (tid >= total2) return;

    const int b  = (int)(tid / H);
    const int v2 = (int)(tid - (long long)b * H);   // float2 index within plane

    // ---- vectorized loads (all plane offsets are multiples of Vv; even) ----
    const float2* q2   = (const float2*)q_in  + (long long)b * 4 * H + v2;
    const float2* qr2  = (const float2*)q_ref + (long long)b * 4 * H + v2;
    const float2* r2   = (const float2*)r_in  + (long long)b * Kv * H + v2;
    const float2* rr2  = (const float2*)r_ref + (long long)b * Kv * H + v2;

    float2 qa[4], qq[4], rv[3], rr[3];
#pragma unroll
    for (int c = 0; c < 4; c++) {
        qa[c] = __ldg(q2  + (long long)c * H);
        qq[c] = __ldg(qr2 + (long long)c * H);
    }
#pragma unroll
    for (int k = 0; k < Kv; k++) {
        rv[k] = __ldg(r2  + (long long)k * H);
        rr[k] = __ldg(rr2 + (long long)k * H);
    }

    const float w0 = __ldg(gate_w + 0);
    const float w1 = __ldg(gate_w + 1);
    const float w2 = __ldg(gate_w + 2);
    const float w3b = __ldg(gate_w + 3) + __ldg(gate_b);

    // ---- compute both lanes ----
    float RnA[9], RnB[9], qoA[4], qoB[4];
    float omA, omB;
    voxel_math(qa[0].x, qa[1].x, qa[2].x, qa[3].x,
               qq[0].x, qq[1].x, qq[2].x, qq[3].x,
               rv[0].x, rv[1].x, rv[2].x,
               rr[0].x, rr[1].x, rr[2].x,
               w0, w1, w2, w3b, RnA, qoA, omA);
    voxel_math(qa[0].y, qa[1].y, qa[2].y, qa[3].y,
               qq[0].y, qq[1].y, qq[2].y, qq[3].y,
               rv[0].y, rv[1].y, rv[2].y,
               rr[0].y, rr[1].y, rr[2].y,
               w0, w1, w2, w3b, RnB, qoB, omB);

    // ---- vectorized stores ----
    const long long OFF_R = (long long)Bv * 9 * H;   // in float2 units
    const long long OFF_Q = OFF_R + (long long)Bv * Kv * H;

    float2* ub = (float2*)out + (long long)b * 9 * H + v2;
#pragma unroll
    for (int m = 0; m < 9; m++) {
        ub[(long long)m * H] = make_float2(RnA[m], RnB[m]);
    }

    float2* rb = (float2*)out + OFF_R + (long long)b * Kv * H + v2;
#pragma unroll
    for (int k = 0; k < Kv; k++) {
        float a  = omA * rv[k].x + (1.0f - omA) * rr[k].x;
        float bb = omB * rv[k].y + (1.0f - omB) * rr[k].y;
        rb[(long long)k * H] = make_float2(a, bb);
    }

    float2* qb = (float2*)out + OFF_Q + (long long)b * 4 * H + v2;
#pragma unroll
    for (int c = 0; c < 4; c++) {
        qb[(long long)c * H] = make_float2(qoA[c], qoB[c]);
    }
}

extern "C" void kernel_launch(void* const* d_in, const int* in_sizes, int n_in,
                              void* d_out, int out_size) {
    const float* r_in   = (const float*)d_in[1];
    const float* q_in   = (const float*)d_in[2];
    const float* r_ref  = (const float*)d_in[4];
    const float* q_ref  = (const float*)d_in[5];
    const float* gate_w = (const float*)d_in[6];
    const float* gate_b = (const float*)d_in[7];
    float* out = (float*)d_out;

    const long long total2 = (long long)Bv * (Vv / 2);   // 884736 threads
    const int threads = 256;
    const int blocks = (int)((total2 + threads - 1) / threads);  // 3456 blocks
    consensus_field_kernel<<<blocks, threads>>>(r_in, q_in, r_ref, q_ref,
                                                gate_w, gate_b, out);
}

// round 10
// speedup vs baseline: 1.2179x; 1.2179x over previous
#include <cuda_runtime.h>
#include <cuda_bf16.h>
#include <math.h>

// ConsensusField3D: per-voxel quaternion slerp + gated blend.
// B=2, K=3, D=H=W=96, V=96^3=884736. 2 voxels/thread (float2).
// R9 -> R10: issue-bound (fma 35% + alu 30%, DRAM only 39%).
// Fix: MUFU intrinsics (__sinf/__expf/__fdividef/rsqrtf), sin(acos(d))=sqrt(1-d^2)
// identity, 32-bit indexing. Precision budget: rel_err 1.2e-7 -> ~1e-6, thr 1e-3.

#define EPSN 1e-6f

static constexpr int Dv = 96;
static constexpr int Vv = Dv * Dv * Dv;   // 884736 (even)
static constexpr int Bv = 2;
static constexpr int Kv = 3;
static constexpr int Hh = Vv / 2;         // float2 elems per plane = 442368

// fast 1/(sqrt(s)+EPS): s >= 0. Floor s to avoid 0*inf=NaN in s*rsqrt(s).
__device__ __forceinline__ float inv_norm_eps(float s) {
    float n = s * rsqrtf(fmaxf(s, 1e-38f));   // sqrt(s), ~2ulp
    return __fdividef(1.0f, n + EPSN);
}

__device__ __forceinline__ void voxel_math(
    float qa0, float qa1, float qa2, float qa3,
    float qq0, float qq1, float qq2, float qq3,
    float rv0, float rv1, float rv2,
    float rr0, float rr1, float rr2,
    float w0, float w1, float w2, float w3b,
    float Rn[9], float qo[4], float& omega)
{
    // normalize quats (n + EPS in denominator, per reference)
    float ia = inv_norm_eps(qa0*qa0 + qa1*qa1 + qa2*qa2 + qa3*qa3);
    float ib = inv_norm_eps(qq0*qq0 + qq1*qq1 + qq2*qq2 + qq3*qq3);
    qa0 *= ia; qa1 *= ia; qa2 *= ia; qa3 *= ia;
    qq0 *= ib; qq1 *= ib; qq2 *= ib; qq3 *= ib;

    float dotq = qa0*qq0 + qa1*qq1 + qa2*qq2 + qa3*qq3;
    float cfeat = fminf(fabsf(dotq), 1.0f);

    float rm  = (rv0 + rv1 + rv2) * (1.0f / 3.0f);
    float rmr = (rr0 + rr1 + rr2) * (1.0f / 3.0f);

    float z = fmaf(rm, w0, fmaf(rmr, w1, fmaf(cfeat, w2, w3b)));
    omega = __fdividef(1.0f, 1.0f + __expf(-z));        // sigmoid
    float t = omega;

    // slerp, reference semantics: flip q1 if d<0; d = clip(|d|,0,1-1e-7)
    float sgn = (dotq < 0.0f) ? -1.0f : 1.0f;
    float dcl = fminf(fabsf(dotq), 1.0f - 1e-7f);
    float theta = acosf(dcl);
    // exact identity: sin(acos(d)) = sqrt(1-d^2)  (theta in [0, pi/2])
    float st2 = fmaxf(1.0f - dcl*dcl, 0.0f);
    float sin_theta = st2 * rsqrtf(fmaxf(st2, 1e-38f));
    bool  small = sin_theta < 1e-4f;
    float inv_sin = small ? 1.0f : __fdividef(1.0f, sin_theta);
    float s_t  = __sinf(t * theta);
    float s_1t = __sinf((1.0f - t) * theta);

    float q1[4]  = { sgn*qq0, sgn*qq1, sgn*qq2, sgn*qq3 };
    float q0a[4] = { qa0, qa1, qa2, qa3 };
#pragma unroll
    for (int c = 0; c < 4; c++) {
        float slerped = (s_t * q0a[c] + s_1t * q1[c]) * inv_sin;
        float lerped  = t * q0a[c] + (1.0f - t) * q1[c];
        qo[c] = small ? lerped : slerped;
    }
    float io = inv_norm_eps(qo[0]*qo[0] + qo[1]*qo[1] + qo[2]*qo[2] + qo[3]*qo[3]);
#pragma unroll
    for (int c = 0; c < 4; c++) qo[c] *= io;

    // quat -> rotation matrix
    float w = qo[0], x = qo[1], y = qo[2], zq = qo[3];
    float xx = x*x, yy = y*y, z2 = zq*zq;
    float xy = x*y, xz = x*zq, yz = y*zq;
    float wx = w*x, wy = w*y, wz = w*zq;

    float R[3][3];
    R[0][0] = 1.0f - 2.0f*(yy + z2);
    R[0][1] = 2.0f*(xy - wz);
    R[0][2] = 2.0f*(xz + wy);
    R[1][0] = 2.0f*(xy + wz);
    R[1][1] = 1.0f - 2.0f*(xx + z2);
    R[1][2] = 2.0f*(yz - wx);
    R[2][0] = 2.0f*(xz - wy);
    R[2][1] = 2.0f*(yz + wx);
    R[2][2] = 1.0f - 2.0f*(xx + yy);

    // column-normalize (axis=-2): Rn stored output-ordered (j*3+i)
#pragma unroll
    for (int j = 0; j < 3; j++) {
        float cn = inv_norm_eps(R[0][j]*R[0][j] + R[1][j]*R[1][j] + R[2][j]*R[2][j]);
#pragma unroll
        for (int i = 0; i < 3; i++) {
            Rn[j*3 + i] = R[i][j] * cn;
        }
    }
}

__global__ __launch_bounds__(256)
void consensus_field_kernel(const float* __restrict__ r_in,
                            const float* __restrict__ q_in,
                            const float* __restrict__ r_ref,
                            const float* __restrict__ q_ref,
                            const float* __restrict__ gate_w,
                            const float* __restrict__ gate_b,
                            float* __restrict__ out)
{
    const int tid = blockIdx.x * blockDim.x + threadIdx.x;
    const int total2 = Bv * Hh;                 // 884736
    if (tid >= total2) return;

    const int b  = tid / Hh;
    const int v2 = tid - b * Hh;                // float2 index within plane

    // ---- vectorized loads (32-bit offsets; everything < 2^27 elems) ----
    const float2* q2  = (const float2*)q_in  + b * 4 * Hh + v2;
    const float2* qr2 = (const float2*)q_ref + b * 4 * Hh + v2;
    const float2* r2  = (const float2*)r_in  + b * Kv * Hh + v2;
    const float2* rr2 = (const float2*)r_ref + b * Kv * Hh + v2;

    float2 qa[4], qq[4], rv[3], rr[3];
#pragma unroll
    for (int c = 0; c < 4; c++) {
        qa[c] = __ldg(q2  + c * Hh);
        qq[c] = __ldg(qr2 + c * Hh);
    }
#pragma unroll
    for (int k = 0; k < Kv; k++) {
        rv[k] = __ldg(r2  + k * Hh);
        rr[k] = __ldg(rr2 + k * Hh);
    }

    const float w0 = __ldg(gate_w + 0);
    const float w1 = __ldg(gate_w + 1);
    const float w2 = __ldg(gate_w + 2);
    const float w3b = __ldg(gate_w + 3) + __ldg(gate_b);

    // ---- compute both lanes ----
    float RnA[9], RnB[9], qoA[4], qoB[4];
    float omA, omB;
    voxel_math(qa[0].x, qa[1].x, qa[2].x, qa[3].x,
               qq[0].x, qq[1].x, qq[2].x, qq[3].x,
               rv[0].x, rv[1].x, rv[2].x,
               rr[0].x, rr[1].x, rr[2].x,
               w0, w1, w2, w3b, RnA, qoA, omA);
    voxel_math(qa[0].y, qa[1].y, qa[2].y, qa[3].y,
               qq[0].y, qq[1].y, qq[2].y, qq[3].y,
               rv[0].y, rv[1].y, rv[2].y,
               rr[0].y, rr[1].y, rr[2].y,
               w0, w1, w2, w3b, RnB, qoB, omB);

    // ---- vectorized stores ----
    const int OFF_R = Bv * 9 * Hh;              // float2 units
    const int OFF_Q = OFF_R + Bv * Kv * Hh;

    float2* ub = (float2*)out + b * 9 * Hh + v2;
#pragma unroll
    for (int m = 0; m < 9; m++) {
        ub[m * Hh] = make_float2(RnA[m], RnB[m]);
    }

    float2* rb = (float2*)out + OFF_R + b * Kv * Hh + v2;
#pragma unroll
    for (int k = 0; k < Kv; k++) {
        float a  = omA * rv[k].x + (1.0f - omA) * rr[k].x;
        float bb = omB * rv[k].y + (1.0f - omB) * rr[k].y;
        rb[k * Hh] = make_float2(a, bb);
    }

    float2* qb = (float2*)out + OFF_Q + b * 4 * Hh + v2;
#pragma unroll
    for (int c = 0; c < 4; c++) {
        qb[c * Hh] = make_float2(qoA[c], qoB[c]);
    }
}

extern "C" void kernel_launch(void* const* d_in, const int* in_sizes, int n_in,
                              void* d_out, int out_size) {
    const float* r_in   = (const float*)d_in[1];
    const float* q_in   = (const float*)d_in[2];
    const float* r_ref  = (const float*)d_in[4];
    const float* q_ref  = (const float*)d_in[5];
    const float* gate_w = (const float*)d_in[6];
    const float* gate_b = (const float*)d_in[7];
    float* out = (float*)d_out;

    const int total2 = Bv * Hh;                 // 884736 threads
    const int threads = 256;
    const int blocks = (total2 + threads - 1) / threads;   // 3456
    consensus_field_kernel<<<blocks, threads>>>(r_in, q_in, r_ref, q_ref,
                                                gate_w, gate_b, out);
}

// round 12
// speedup vs baseline: 1.4830x; 1.2177x over previous
#include <cuda_runtime.h>
#include <cuda_bf16.h>
#include <math.h>

// ConsensusField3D: per-voxel quaternion slerp + gated blend.
// B=2, K=3, D=H=W=96, V=96^3=884736. 2 voxels/thread (float2).
// R10 -> R11 (issue-bound: issue 63%, fma 34%, DRAM 51%):
//  - lerp branch is dead code (clip d<=1-1e-7 => sin_theta >= 4.47e-4 > 1e-4)
//  - norms: 1/(sqrt(s)+eps) -> rsqrtf(s)  (rel diff ~1e-6, budget 1e-3)
//  - acosf -> A&S 4.4.45 sqrt(1-x)*poly3(x), |err|<=6.7e-5 rad

static constexpr int Dv = 96;
static constexpr int Vv = Dv * Dv * Dv;   // 884736
static constexpr int Bv = 2;
static constexpr int Kv = 3;
static constexpr int Hh = Vv / 2;         // float2 elems per plane = 442368

__device__ __forceinline__ void voxel_math(
    float qa0, float qa1, float qa2, float qa3,
    float qq0, float qq1, float qq2, float qq3,
    float rv0, float rv1, float rv2,
    float rr0, float rr1, float rr2,
    float w0, float w1, float w2, float w3b,
    float Rn[9], float qo[4], float& omega)
{
    // normalize quats: 1/(||q||+eps) ~= rsqrt(||q||^2), rel diff ~1e-6
    float ia = rsqrtf(qa0*qa0 + qa1*qa1 + qa2*qa2 + qa3*qa3);
    float ib = rsqrtf(qq0*qq0 + qq1*qq1 + qq2*qq2 + qq3*qq3);
    qa0 *= ia; qa1 *= ia; qa2 *= ia; qa3 *= ia;
    qq0 *= ib; qq1 *= ib; qq2 *= ib; qq3 *= ib;

    float dotq = qa0*qq0 + qa1*qq1 + qa2*qq2 + qa3*qq3;
    float ad   = fabsf(dotq);
    float cfeat = fminf(ad, 1.0f);

    float rm  = (rv0 + rv1 + rv2) * (1.0f / 3.0f);
    float rmr = (rr0 + rr1 + rr2) * (1.0f / 3.0f);

    float z = fmaf(rm, w0, fmaf(rmr, w1, fmaf(cfeat, w2, w3b)));
    omega = __fdividef(1.0f, 1.0f + __expf(-z));        // sigmoid
    float t = omega;

    // slerp. d = clip(|dot|, 0, 1-1e-7); flip q1 if dot<0.
    float sgn = (dotq < 0.0f) ? -1.0f : 1.0f;
    float dcl = fminf(ad, 1.0f - 1e-7f);

    // theta = acos(dcl) via A&S 4.4.45: sqrt(1-x)*poly3(x), err <= 6.7e-5
    float omx = 1.0f - dcl;                              // >= 1e-7
    float sq_omx = omx * rsqrtf(omx);                    // sqrt(1-x)
    float poly = fmaf(fmaf(fmaf(-0.0187293f, dcl, 0.0742610f),
                           dcl, -0.2121144f), dcl, 1.5707288f);
    float theta = sq_omx * poly;

    // sin(theta) exactly: sqrt(1-d^2) = sqrt((1-d)(1+d)) >= 4.47e-4 (never "small")
    float st2 = omx * (1.0f + dcl);
    float inv_sin = rsqrtf(st2);                         // 1/sin(theta)

    float s_t  = __sinf(t * theta);
    float s_1t = __sinf((1.0f - t) * theta);
    float c0 = s_t * inv_sin;                            // weight on q0
    float c1 = s_1t * inv_sin * sgn;                     // weight on (flipped) q1

    qo[0] = c0 * qa0 + c1 * qq0;
    qo[1] = c0 * qa1 + c1 * qq1;
    qo[2] = c0 * qa2 + c1 * qq2;
    qo[3] = c0 * qa3 + c1 * qq3;

    float io = rsqrtf(qo[0]*qo[0] + qo[1]*qo[1] + qo[2]*qo[2] + qo[3]*qo[3]);
#pragma unroll
    for (int c = 0; c < 4; c++) qo[c] *= io;

    // quat -> rotation matrix
    float w = qo[0], x = qo[1], y = qo[2], zq = qo[3];
    float xx = x*x, yy = y*y, z2 = zq*zq;
    float xy = x*y, xz = x*zq, yz = y*zq;
    float wx = w*x, wy = w*y, wz = w*zq;

    float R[3][3];
    R[0][0] = 1.0f - 2.0f*(yy + z2);
    R[0][1] = 2.0f*(xy - wz);
    R[0][2] = 2.0f*(xz + wy);
    R[1][0] = 2.0f*(xy + wz);
    R[1][1] = 1.0f - 2.0f*(xx + z2);
    R[1][2] = 2.0f*(yz - wx);
    R[2][0] = 2.0f*(xz - wy);
    R[2][1] = 2.0f*(yz + wx);
    R[2][2] = 1.0f - 2.0f*(xx + yy);

    // column-normalize (axis=-2); Rn stored output-ordered (j*3+i)
#pragma unroll
    for (int j = 0; j < 3; j++) {
        float cn = rsqrtf(R[0][j]*R[0][j] + R[1][j]*R[1][j] + R[2][j]*R[2][j]);
#pragma unroll
        for (int i = 0; i < 3; i++) {
            Rn[j*3 + i] = R[i][j] * cn;
        }
    }
}

__global__ __launch_bounds__(256)
void consensus_field_kernel(const float* __restrict__ r_in,
                            const float* __restrict__ q_in,
                            const float* __restrict__ r_ref,
                            const float* __restrict__ q_ref,
                            const float* __restrict__ gate_w,
                            const float* __restrict__ gate_b,
                            float* __restrict__ out)
{
    const int tid = blockIdx.x * blockDim.x + threadIdx.x;
    const int total2 = Bv * Hh;                 // 884736
    if (tid >= total2) return;

    const int b  = tid / Hh;
    const int v2 = tid - b * Hh;

    const float2* q2  = (const float2*)q_in  + b * 4 * Hh + v2;
    const float2* qr2 = (const float2*)q_ref + b * 4 * Hh + v2;
    const float2* r2  = (const float2*)r_in  + b * Kv * Hh + v2;
    const float2* rr2 = (const float2*)r_ref + b * Kv * Hh + v2;

    float2 qa[4], qq[4], rv[3], rr[3];
#pragma unroll
    for (int c = 0; c < 4; c++) {
        qa[c] = __ldg(q2  + c * Hh);
        qq[c] = __ldg(qr2 + c * Hh);
    }
#pragma unroll
    for (int k = 0; k < Kv; k++) {
        rv[k] = __ldg(r2  + k * Hh);
        rr[k] = __ldg(rr2 + k * Hh);
    }

    const float w0 = __ldg(gate_w + 0);
    const float w1 = __ldg(gate_w + 1);
    const float w2 = __ldg(gate_w + 2);
    const float w3b = __ldg(gate_w + 3) + __ldg(gate_b);

    float RnA[9], RnB[9], qoA[4], qoB[4];
    float omA, omB;
    voxel_math(qa[0].x, qa[1].x, qa[2].x, qa[3].x,
               qq[0].x, qq[1].x, qq[2].x, qq[3].x,
               rv[0].x, rv[1].x, rv[2].x,
               rr[0].x, rr[1].x, rr[2].x,
               w0, w1, w2, w3b, RnA, qoA, omA);
    voxel_math(qa[0].y, qa[1].y, qa[2].y, qa[3].y,
               qq[0].y, qq[1].y, qq[2].y, qq[3].y,
               rv[0].y, rv[1].y, rv[2].y,
               rr[0].y, rr[1].y, rr[2].y,
               w0, w1, w2, w3b, RnB, qoB, omB);

    const int OFF_R = Bv * 9 * Hh;              // float2 units
    const int OFF_Q = OFF_R + Bv * Kv * Hh;

    float2* ub = (float2*)out + b * 9 * Hh + v2;
#pragma unroll
    for (int m = 0; m < 9; m++) {
        ub[m * Hh] = make_float2(RnA[m], RnB[m]);
    }

    float2* rb = (float2*)out + OFF_R + b * Kv * Hh + v2;
#pragma unroll
    for (int k = 0; k < Kv; k++) {
        float a  = omA * rv[k].x + (1.0f - omA) * rr[k].x;
        float bb = omB * rv[k].y + (1.0f - omB) * rr[k].y;
        rb[k * Hh] = make_float2(a, bb);
    }

    float2* qb = (float2*)out + OFF_Q + b * 4 * Hh + v2;
#pragma unroll
    for (int c = 0; c < 4; c++) {
        qb[c * Hh] = make_float2(qoA[c], qoB[c]);
    }
}

extern "C" void kernel_launch(void* const* d_in, const int* in_sizes, int n_in,
                              void* d_out, int out_size) {
    const float* r_in   = (const float*)d_in[1];
    const float* q_in   = (const float*)d_in[2];
    const float* r_ref  = (const float*)d_in[4];
    const float* q_ref  = (const float*)d_in[5];
    const float* gate_w = (const float*)d_in[6];
    const float* gate_b = (const float*)d_in[7];
    float* out = (float*)d_out;

    const int total2 = Bv * Hh;                 // 884736 threads
    const int threads = 256;
    const int blocks = (total2 + threads - 1) / threads;   // 3456
    consensus_field_kernel<<<blocks, threads>>>(r_in, q_in, r_ref, q_ref,
                                                gate_w, gate_b, out);
}